// round 6
// baseline (speedup 1.0000x reference)
#include <cuda_runtime.h>
#include <math.h>

#define KTAGS 64
#define DDIM  128
#define VWORDS 50000
#define NV   (VWORDS + 2)
#define BATCHN 2048
#define TLEN 256
#define BOS_TAG 63
#define EOS_TAG 62
#define TINYV 1e-45f

#define NWARP 4
#define SPW   2                 // sentences per warp
#define SPB   (NWARP * SPW)     // 8 sentences per CTA
#define ASTR  68
#define NPAIR (KTAGS / 2)       // 32 alpha pairs
#define HREG  16                // row-pairs 0..15 (rows 0..31) in registers
#define HSM   16                // row-pairs 16..31 (rows 32..63) in smem

typedef unsigned long long u64;

__device__ __forceinline__ u64 pack2(float lo, float hi) {
    u64 r; asm("mov.b64 %0,{%1,%2};" : "=l"(r) : "f"(lo), "f"(hi)); return r;
}
__device__ __forceinline__ u64 fma2(u64 a, u64 b, u64 c) {
    u64 d; asm("fma.rn.f32x2 %0,%1,%2,%3;" : "=l"(d) : "l"(a), "l"(b), "l"(c)); return d;
}
__device__ __forceinline__ u64 mul2(u64 a, u64 b) {
    u64 d; asm("mul.rn.f32x2 %0,%1,%2;" : "=l"(d) : "l"(a), "l"(b)); return d;
}
__device__ __forceinline__ float2 unpack2(u64 v) {
    float2 f; asm("mov.b64 {%0,%1},%2;" : "=f"(f.x), "=f"(f.y) : "l"(v)); return f;
}

// Scratch (static device global; no dynamic allocation)
__device__ float g_Bt[(size_t)NV * KTAGS];   // emission table, word-major [w][k]

// ---------------------------------------------------------------------------
// Kernel 1: emission table g_Bt[w][k] = exp(dot(ThetaB[k,:], E[w,:]))
// ---------------------------------------------------------------------------
__global__ __launch_bounds__(256) void emit_table_kernel(
        const float* __restrict__ ThetaB, const float* __restrict__ E) {
    __shared__ __align__(16) float sE[64 * 65];
    __shared__ __align__(16) float sTh[64 * ASTR];

    int tid = threadIdx.x;
    int wq  = tid & 15;
    int kq  = tid >> 4;
    int w0  = blockIdx.x * 64;

    u64 acc[4][2];
#pragma unroll
    for (int a = 0; a < 4; a++) { acc[a][0] = 0ull; acc[a][1] = 0ull; }

    for (int dc = 0; dc < 2; dc++) {
        for (int idx = tid; idx < 64 * 64; idx += 256) {
            int k = idx >> 6, dl = idx & 63;
            sTh[dl * ASTR + k] = ThetaB[k * DDIM + dc * 64 + dl];
        }
        for (int idx = tid; idx < 64 * 64; idx += 256) {
            int w = idx >> 6, dl = idx & 63;
            int wg = w0 + w;
            sE[w * 65 + dl] = (wg < NV) ? E[(size_t)wg * DDIM + dc * 64 + dl] : 0.0f;
        }
        __syncthreads();

#pragma unroll 8
        for (int dl = 0; dl < 64; dl++) {
            ulonglong2 th = *(const ulonglong2*)&sTh[dl * ASTR + kq * 4];
#pragma unroll
            for (int ww = 0; ww < 4; ww++) {
                float e = sE[(wq * 4 + ww) * 65 + dl];
                u64 ep = pack2(e, e);
                acc[ww][0] = fma2(ep, th.x, acc[ww][0]);
                acc[ww][1] = fma2(ep, th.y, acc[ww][1]);
            }
        }
        __syncthreads();
    }

#pragma unroll
    for (int ww = 0; ww < 4; ww++) {
        int w = w0 + wq * 4 + ww;
        if (w < NV) {
            float2 p0 = unpack2(acc[ww][0]);
            float2 p1 = unpack2(acc[ww][1]);
            float4 r;
            r.x = expf(p0.x); r.y = expf(p0.y);
            r.z = expf(p1.x); r.w = expf(p1.y);
            if (kq == 15) { r.z = TINYV; r.w = TINYV; }
            *(float4*)&g_Bt[(size_t)w * KTAGS + kq * 4] = r;
        }
    }
}

// ---------------------------------------------------------------------------
// Kernel 2: forward scan, dot-product f32x2 form with HYBRID A placement.
// Lane l owns output tags (2l, 2l+1).
//   rows  0..31 of A': registers AL/AH[16]  (64 regs)
//   rows 32..63 of A': smem sAhi[i][j] = pack(A'[32+2i][j], A'[33+2i][j]),
//     lane l streams (cols 2l,2l+1) as one conflict-free LDS.128 per i,
//     shared across both sentences.
// Frees ~60 regs vs all-register A so ptxas can pipeline LDS/LDG deeply.
// ---------------------------------------------------------------------------
__global__ __launch_bounds__(128, 2) void crf_scan_kernel(
        const float* __restrict__ WA,
        const int* __restrict__ words, float* __restrict__ out) {
    __shared__ __align__(16) u64 sAl[NWARP][2][SPW][NPAIR];   // 4 KB
    __shared__ __align__(16) u64 sAhi[HSM][KTAGS];            // 8 KB
    __shared__ int sWT[TLEN][SPB];                             // 8 KB

    int tid  = threadIdx.x;
    int warp = tid >> 5;
    int lane = tid & 31;
    int s0   = blockIdx.x * SPB;

    // words -> smem transposed: sWT[t][s]
    for (int idx = tid; idx < SPB * TLEN; idx += 128) {
        int ss = idx >> 8, t = idx & (TLEN - 1);
        sWT[t][ss] = words[(size_t)(s0 + ss) * TLEN + t];
    }

    // upper-half A' into smem: sAhi[i][j] = (A'[32+2i][j], A'[33+2i][j])
    for (int idx = tid; idx < HSM * KTAGS; idx += 128) {
        int i = idx >> 6, j = idx & 63;
        float v0, v1;
        if (j == BOS_TAG) { v0 = 0.0f; v1 = 0.0f; }
        else {
            v0 = expf(__ldg(&WA[(32 + 2 * i) * KTAGS + j])) * (1.0f / 64.0f);
            v1 = expf(__ldg(&WA[(33 + 2 * i) * KTAGS + j])) * (1.0f / 64.0f);
        }
        sAhi[i][j] = pack2(v0, v1);
    }

    // lower-half A' into registers (rows 0..31), dot-product layout:
    // AL[i] = (A'[2i][2l], A'[2i+1][2l]), AH[i] = same for col 2l+1.
    int jL = 2 * lane, jH = 2 * lane + 1;
    u64 AL[HREG], AH[HREG];
#pragma unroll
    for (int i = 0; i < HREG; i++) {
        float l0 = expf(__ldg(&WA[(2 * i)     * KTAGS + jL])) * (1.0f / 64.0f);
        float l1 = expf(__ldg(&WA[(2 * i + 1) * KTAGS + jL])) * (1.0f / 64.0f);
        AL[i] = pack2(l0, l1);
        float h0, h1;
        if (jH == BOS_TAG) { h0 = 0.0f; h1 = 0.0f; }
        else {
            h0 = expf(__ldg(&WA[(2 * i)     * KTAGS + jH])) * (1.0f / 64.0f);
            h1 = expf(__ldg(&WA[(2 * i + 1) * KTAGS + jH])) * (1.0f / 64.0f);
        }
        AH[i] = pack2(h0, h1);
    }

    // EOS column entries for this lane's two tags
    float eosL = expf(__ldg(&WA[jL * KTAGS + EOS_TAG])) * (1.0f / 64.0f);
    float eosH = expf(__ldg(&WA[jH * KTAGS + EOS_TAG])) * (1.0f / 64.0f);

    // alpha0: pair 31 = (alpha[62], alpha[63]) = (0, 1); all else 0
#pragma unroll
    for (int s = 0; s < SPW; s++)
        sAl[warp][0][s][lane] = (lane == 31) ? pack2(0.0f, 1.0f) : 0ull;
    __syncthreads();   // covers sWT and sAhi too

    int sbase = warp * SPW;

    // prefetch emissions for t=1
    u64 e[SPW];
#pragma unroll
    for (int s = 0; s < SPW; s++) {
        int w = sWT[1][sbase + s];
        e[s] = __ldg(((const u64*)g_Bt) + ((size_t)w << 5) + lane);
    }

    int p = 0;
    for (int t = 1; t <= TLEN - 2; ++t) {
        // prefetch next step's emissions (t=254 reads pos 255: valid, unused)
        u64 en[SPW];
#pragma unroll
        for (int s = 0; s < SPW; s++) {
            int wn = sWT[t + 1][sbase + s];
            en[s] = __ldg(((const u64*)g_Bt) + ((size_t)wn << 5) + lane);
        }

        u64 accL[SPW], accH[SPW];
#pragma unroll
        for (int s = 0; s < SPW; s++) { accL[s] = 0ull; accH[s] = 0ull; }

        // register half: alpha pairs 0..15 (rows 0..31)
#pragma unroll
        for (int i = 0; i < HREG; i += 2) {
#pragma unroll
            for (int s = 0; s < SPW; s++) {
                ulonglong2 v = *(const ulonglong2*)&sAl[warp][p][s][i];
                accL[s] = fma2(v.x, AL[i],     accL[s]);
                accH[s] = fma2(v.x, AH[i],     accH[s]);
                accL[s] = fma2(v.y, AL[i + 1], accL[s]);
                accH[s] = fma2(v.y, AH[i + 1], accH[s]);
            }
        }

        // smem half: alpha pairs 16..31 (rows 32..63); A streamed per step,
        // one LDS.128 per i shared across both sentences.
#pragma unroll
        for (int i = 0; i < HSM; i += 2) {
            ulonglong2 a0 = *(const ulonglong2*)&sAhi[i][jL];      // (AL_i, AH_i)
            ulonglong2 a1 = *(const ulonglong2*)&sAhi[i + 1][jL];
#pragma unroll
            for (int s = 0; s < SPW; s++) {
                ulonglong2 v = *(const ulonglong2*)&sAl[warp][p][s][HREG + i];
                accL[s] = fma2(v.x, a0.x, accL[s]);
                accH[s] = fma2(v.x, a0.y, accH[s]);
                accL[s] = fma2(v.y, a1.x, accL[s]);
                accH[s] = fma2(v.y, a1.y, accH[s]);
            }
        }

        // fold lo+hi, multiply by emissions, store packed pair
#pragma unroll
        for (int s = 0; s < SPW; s++) {
            float2 fL = unpack2(accL[s]);
            float2 fH = unpack2(accH[s]);
            u64 r = mul2(pack2(fL.x + fL.y, fH.x + fH.y), e[s]);
            sAl[warp][p ^ 1][s][lane] = r;
            e[s] = en[s];
        }
        __syncwarp();
        p ^= 1;
    }

    // final transition into EOS
#pragma unroll
    for (int s = 0; s < SPW; s++) {
        float2 a = unpack2(sAl[warp][p][s][lane]);
        float z = a.x * eosL + a.y * eosH;
#pragma unroll
        for (int off = 16; off; off >>= 1)
            z += __shfl_xor_sync(0xffffffffu, z, off);
        if (lane == 0) {
            // + 255 * log(64) = 1530 * ln2 (fixed-scaling compensation)
            out[s0 + sbase + s] = logf(z) + 1060.5151862567153f;
        }
    }
}

// ---------------------------------------------------------------------------
extern "C" void kernel_launch(void* const* d_in, const int* in_sizes, int n_in,
                              void* d_out, int out_size) {
    const int*   words  = nullptr;
    const float* ThetaB = nullptr;
    const float* WA     = nullptr;
    const float* E      = nullptr;
    for (int i = 0; i < n_in; i++) {
        switch (in_sizes[i]) {
            case BATCHN * TLEN:   words  = (const int*)d_in[i];   break;
            case KTAGS * DDIM:    ThetaB = (const float*)d_in[i]; break;
            case KTAGS * KTAGS:   WA     = (const float*)d_in[i]; break;
            case NV * DDIM:       E      = (const float*)d_in[i]; break;
        }
    }
    float* out = (float*)d_out;

    emit_table_kernel<<<(NV + 63) / 64, 256>>>(ThetaB, E);
    crf_scan_kernel<<<BATCHN / SPB, 128>>>(WA, words, out);
}

// round 7
// speedup vs baseline: 1.2971x; 1.2971x over previous
#include <cuda_runtime.h>
#include <math.h>
#include <stdint.h>

#define KTAGS 64
#define DDIM  128
#define VWORDS 50000
#define NV   (VWORDS + 2)
#define BATCHN 2048
#define TLEN 256
#define BOS_TAG 63
#define EOS_TAG 62
#define TINYV 1e-45f
#define ASTR  68

typedef unsigned long long u64;

__device__ __forceinline__ u64 pack2(float lo, float hi) {
    u64 r; asm("mov.b64 %0,{%1,%2};" : "=l"(r) : "f"(lo), "f"(hi)); return r;
}
__device__ __forceinline__ u64 fma2(u64 a, u64 b, u64 c) {
    u64 d; asm("fma.rn.f32x2 %0,%1,%2,%3;" : "=l"(d) : "l"(a), "l"(b), "l"(c)); return d;
}
__device__ __forceinline__ float2 unpack2(u64 v) {
    float2 f; asm("mov.b64 {%0,%1},%2;" : "=f"(f.x), "=f"(f.y) : "l"(v)); return f;
}
// pack two fp32 -> bf16x2 (lo = second operand)
__device__ __forceinline__ uint32_t cvt_bf16x2(float hi, float lo) {
    uint32_t r; asm("cvt.rn.bf16x2.f32 %0, %1, %2;" : "=r"(r) : "f"(hi), "f"(lo)); return r;
}
// D(16x8,f32) += A(16x16,bf16) @ B(16x8,bf16)
__device__ __forceinline__ void mma16816(float& d0, float& d1, float& d2, float& d3,
        uint32_t a0, uint32_t a1, uint32_t a2, uint32_t a3,
        uint32_t b0, uint32_t b1) {
    asm("mma.sync.aligned.m16n8k16.row.col.f32.bf16.bf16.f32 "
        "{%0,%1,%2,%3}, {%4,%5,%6,%7}, {%8,%9}, {%0,%1,%2,%3};"
        : "+f"(d0), "+f"(d1), "+f"(d2), "+f"(d3)
        : "r"(a0), "r"(a1), "r"(a2), "r"(a3), "r"(b0), "r"(b1));
}

// Scratch (static device global; no dynamic allocation)
__device__ float g_Bt[(size_t)NV * KTAGS];   // emission table, word-major [w][k]

// ---------------------------------------------------------------------------
// Kernel 1: emission table g_Bt[w][k] = exp(dot(ThetaB[k,:], E[w,:]))
// ---------------------------------------------------------------------------
__global__ __launch_bounds__(256) void emit_table_kernel(
        const float* __restrict__ ThetaB, const float* __restrict__ E) {
    __shared__ __align__(16) float sE[64 * 65];
    __shared__ __align__(16) float sTh[64 * ASTR];

    int tid = threadIdx.x;
    int wq  = tid & 15;
    int kq  = tid >> 4;
    int w0  = blockIdx.x * 64;

    u64 acc[4][2];
#pragma unroll
    for (int a = 0; a < 4; a++) { acc[a][0] = 0ull; acc[a][1] = 0ull; }

    for (int dc = 0; dc < 2; dc++) {
        for (int idx = tid; idx < 64 * 64; idx += 256) {
            int k = idx >> 6, dl = idx & 63;
            sTh[dl * ASTR + k] = ThetaB[k * DDIM + dc * 64 + dl];
        }
        for (int idx = tid; idx < 64 * 64; idx += 256) {
            int w = idx >> 6, dl = idx & 63;
            int wg = w0 + w;
            sE[w * 65 + dl] = (wg < NV) ? E[(size_t)wg * DDIM + dc * 64 + dl] : 0.0f;
        }
        __syncthreads();

#pragma unroll 8
        for (int dl = 0; dl < 64; dl++) {
            ulonglong2 th = *(const ulonglong2*)&sTh[dl * ASTR + kq * 4];
#pragma unroll
            for (int ww = 0; ww < 4; ww++) {
                float e = sE[(wq * 4 + ww) * 65 + dl];
                u64 ep = pack2(e, e);
                acc[ww][0] = fma2(ep, th.x, acc[ww][0]);
                acc[ww][1] = fma2(ep, th.y, acc[ww][1]);
            }
        }
        __syncthreads();
    }

#pragma unroll
    for (int ww = 0; ww < 4; ww++) {
        int w = w0 + wq * 4 + ww;
        if (w < NV) {
            float2 p0 = unpack2(acc[ww][0]);
            float2 p1 = unpack2(acc[ww][1]);
            float4 r;
            r.x = expf(p0.x); r.y = expf(p0.y);
            r.z = expf(p1.x); r.w = expf(p1.y);
            if (kq == 15) { r.z = TINYV; r.w = TINYV; }
            *(float4*)&g_Bt[(size_t)w * KTAGS + kq * 4] = r;
        }
    }
}

// ---------------------------------------------------------------------------
// Kernel 2: forward scan via mma.sync m16n8k16 bf16.
// One warp per CTA, 16 sentences per warp (rows of the MMA M dim).
//   A fragment  = alpha_{t-1} (16 x 64 bf16, 4 k-chunks)
//   B fragments = A' (64 x 64 bf16, 4 kc x 8 nb, stationary in 64 regs)
//   D (fp32)    = alpha_{t-1} @ A'  -> x emis (fp32) -> cvt bf16 -> next A.
// D(m16n8) layout == A(m16k16) layout (rows g/g+8, cols 2q/2q+1): no shuffles.
// lane: g = lane>>2 (row/sentence 0..7; +8 for second), q = lane&3.
// ---------------------------------------------------------------------------
__global__ __launch_bounds__(32, 1) void crf_scan_kernel(
        const float* __restrict__ WA,
        const int* __restrict__ words, float* __restrict__ out) {
    __shared__ __align__(16) float sWA[KTAGS * KTAGS];   // 16 KB
    __shared__ int sWT[TLEN][16];                         // transposed words, 16 KB

    int lane = threadIdx.x;
    int g  = lane >> 2;       // 0..7
    int q  = lane & 3;        // 0..3
    int s0 = blockIdx.x * 16;

    // stage WA (float4) and words (transposed)
    for (int idx = lane; idx < KTAGS * KTAGS / 4; idx += 32)
        ((float4*)sWA)[idx] = ((const float4*)WA)[idx];
    for (int idx = lane; idx < 16 * TLEN; idx += 32) {
        int s = idx >> 8, tt = idx & (TLEN - 1);
        sWT[tt][s] = words[(size_t)(s0 + s) * TLEN + tt];
    }
    __syncwarp();

    // B fragments: Bf[kc][nb] covers A' rows 16kc..+15, cols 8nb..+7.
    // b0 = (rows 16kc+2q, +1 ; col 8nb+g), b1 = rows +8. col 63 (BOS) -> 0.
    uint32_t Bf[4][8][2];
    {
        int n = 0; // filled per nb below
#pragma unroll
        for (int nb = 0; nb < 8; nb++) {
            n = 8 * nb + g;
            bool bos = (n == BOS_TAG);
#pragma unroll
            for (int kc = 0; kc < 4; kc++) {
                int k0 = 16 * kc + 2 * q;
                float v0 = bos ? 0.0f : expf(sWA[(k0)     * KTAGS + n]) * 0.015625f;
                float v1 = bos ? 0.0f : expf(sWA[(k0 + 1) * KTAGS + n]) * 0.015625f;
                float v8 = bos ? 0.0f : expf(sWA[(k0 + 8) * KTAGS + n]) * 0.015625f;
                float v9 = bos ? 0.0f : expf(sWA[(k0 + 9) * KTAGS + n]) * 0.015625f;
                Bf[kc][nb][0] = cvt_bf16x2(v1, v0);
                Bf[kc][nb][1] = cvt_bf16x2(v9, v8);
            }
        }
    }

    // alpha_1[s][j] = A'[BOS][j] * emis(w(s,1))[j]   (fp32, then bf16 A frags)
    uint32_t Af[4][4];
    {
        int w1g  = sWT[1][g];
        int w1g8 = sWT[1][8 + g];
#pragma unroll
        for (int kc = 0; kc < 4; kc++) {
            int j0 = 16 * kc + 2 * q;
            float rb0 = (j0     == BOS_TAG) ? 0.0f : expf(sWA[BOS_TAG * KTAGS + j0])     * 0.015625f;
            float rb1 = (j0 + 1 == BOS_TAG) ? 0.0f : expf(sWA[BOS_TAG * KTAGS + j0 + 1]) * 0.015625f;
            float rb8 = (j0 + 8 == BOS_TAG) ? 0.0f : expf(sWA[BOS_TAG * KTAGS + j0 + 8]) * 0.015625f;
            float rb9 = (j0 + 9 == BOS_TAG) ? 0.0f : expf(sWA[BOS_TAG * KTAGS + j0 + 9]) * 0.015625f;
            float2 eL  = *(const float2*)(g_Bt + (size_t)w1g  * KTAGS + j0);
            float2 eH  = *(const float2*)(g_Bt + (size_t)w1g  * KTAGS + j0 + 8);
            float2 mL  = *(const float2*)(g_Bt + (size_t)w1g8 * KTAGS + j0);
            float2 mH  = *(const float2*)(g_Bt + (size_t)w1g8 * KTAGS + j0 + 8);
            Af[kc][0] = cvt_bf16x2(rb1 * eL.y, rb0 * eL.x);   // row g,  cols j0,j0+1
            Af[kc][1] = cvt_bf16x2(rb1 * mL.y, rb0 * mL.x);   // row g+8
            Af[kc][2] = cvt_bf16x2(rb9 * eH.y, rb8 * eH.x);   // row g,  cols j0+8,j0+9
            Af[kc][3] = cvt_bf16x2(rb9 * mH.y, rb8 * mH.x);   // row g+8
        }
    }

    // preload emissions for step t=2: eg[nb] = emis(w(g,2))[8nb+2q, +1], eg8 same for g+8
    float2 eg[8], eg8[8];
    {
        int w2g  = sWT[2][g];
        int w2g8 = sWT[2][8 + g];
#pragma unroll
        for (int nb = 0; nb < 8; nb++) {
            eg[nb]  = *(const float2*)(g_Bt + (size_t)w2g  * KTAGS + 8 * nb + 2 * q);
            eg8[nb] = *(const float2*)(g_Bt + (size_t)w2g8 * KTAGS + 8 * nb + 2 * q);
        }
    }

    float d[8][4];   // persists after loop for the final reduction

    for (int t = 2; t <= TLEN - 2; ++t) {
        // prefetch emissions for step t+1 (t=254 reads pos 255: valid, unused)
        float2 ng[8], ng8[8];
        {
            int wn  = sWT[t + 1][g];
            int wn8 = sWT[t + 1][8 + g];
#pragma unroll
            for (int nb = 0; nb < 8; nb++) {
                ng[nb]  = *(const float2*)(g_Bt + (size_t)wn  * KTAGS + 8 * nb + 2 * q);
                ng8[nb] = *(const float2*)(g_Bt + (size_t)wn8 * KTAGS + 8 * nb + 2 * q);
            }
        }

        // D = alpha_{t-1} @ A'
#pragma unroll
        for (int nb = 0; nb < 8; nb++) {
            d[nb][0] = 0.0f; d[nb][1] = 0.0f; d[nb][2] = 0.0f; d[nb][3] = 0.0f;
#pragma unroll
            for (int kc = 0; kc < 4; kc++)
                mma16816(d[nb][0], d[nb][1], d[nb][2], d[nb][3],
                         Af[kc][0], Af[kc][1], Af[kc][2], Af[kc][3],
                         Bf[kc][nb][0], Bf[kc][nb][1]);
        }

        // x emissions (fp32)
#pragma unroll
        for (int nb = 0; nb < 8; nb++) {
            d[nb][0] *= eg[nb].x;  d[nb][1] *= eg[nb].y;
            d[nb][2] *= eg8[nb].x; d[nb][3] *= eg8[nb].y;
            eg[nb] = ng[nb]; eg8[nb] = ng8[nb];
        }

        // D(m16n8) -> A(m16k16): direct per-thread remap (nb pair 2kc, 2kc+1)
        if (t < TLEN - 2) {
#pragma unroll
            for (int kc = 0; kc < 4; kc++) {
                Af[kc][0] = cvt_bf16x2(d[2 * kc][1],     d[2 * kc][0]);
                Af[kc][1] = cvt_bf16x2(d[2 * kc][3],     d[2 * kc][2]);
                Af[kc][2] = cvt_bf16x2(d[2 * kc + 1][1], d[2 * kc + 1][0]);
                Af[kc][3] = cvt_bf16x2(d[2 * kc + 1][3], d[2 * kc + 1][2]);
            }
        }
    }

    // final transition into EOS: z = sum_j alpha254[j] * A'[j][EOS]
    {
        float zg = 0.0f, zg8 = 0.0f;
#pragma unroll
        for (int nb = 0; nb < 8; nb++) {
            int j0 = 8 * nb + 2 * q;
            float e0 = expf(sWA[(j0)     * KTAGS + EOS_TAG]) * 0.015625f;
            float e1 = expf(sWA[(j0 + 1) * KTAGS + EOS_TAG]) * 0.015625f;
            zg  += d[nb][0] * e0 + d[nb][1] * e1;
            zg8 += d[nb][2] * e0 + d[nb][3] * e1;
        }
        // reduce across the 4 lanes (q = 0..3) sharing each row
        zg  += __shfl_xor_sync(0xffffffffu, zg, 1);
        zg  += __shfl_xor_sync(0xffffffffu, zg, 2);
        zg8 += __shfl_xor_sync(0xffffffffu, zg8, 1);
        zg8 += __shfl_xor_sync(0xffffffffu, zg8, 2);
        if (q == 0) {
            // + 255 * log(64) = 1530 * ln2 (fixed-scaling compensation)
            out[s0 + g]     = logf(zg)  + 1060.5151862567153f;
            out[s0 + 8 + g] = logf(zg8) + 1060.5151862567153f;
        }
    }
}

// ---------------------------------------------------------------------------
extern "C" void kernel_launch(void* const* d_in, const int* in_sizes, int n_in,
                              void* d_out, int out_size) {
    const int*   words  = nullptr;
    const float* ThetaB = nullptr;
    const float* WA     = nullptr;
    const float* E      = nullptr;
    for (int i = 0; i < n_in; i++) {
        switch (in_sizes[i]) {
            case BATCHN * TLEN:   words  = (const int*)d_in[i];   break;
            case KTAGS * DDIM:    ThetaB = (const float*)d_in[i]; break;
            case KTAGS * KTAGS:   WA     = (const float*)d_in[i]; break;
            case NV * DDIM:       E      = (const float*)d_in[i]; break;
        }
    }
    float* out = (float*)d_out;

    emit_table_kernel<<<(NV + 63) / 64, 256>>>(ThetaB, E);
    crf_scan_kernel<<<BATCHN / 16, 32>>>(WA, words, out);
}

// round 8
// speedup vs baseline: 1.9616x; 1.5123x over previous
#include <cuda_runtime.h>
#include <math.h>
#include <stdint.h>

#define KTAGS 64
#define DDIM  128
#define VWORDS 50000
#define NV   (VWORDS + 2)
#define BATCHN 2048
#define TLEN 256
#define BOS_TAG 63
#define EOS_TAG 62
#define TINYV 1e-45f
#define ASTR  68
#define SCL   0.015625f   // 1/64 folded scaling

typedef unsigned long long u64;

__device__ __forceinline__ u64 pack2(float lo, float hi) {
    u64 r; asm("mov.b64 %0,{%1,%2};" : "=l"(r) : "f"(lo), "f"(hi)); return r;
}
__device__ __forceinline__ u64 fma2(u64 a, u64 b, u64 c) {
    u64 d; asm("fma.rn.f32x2 %0,%1,%2,%3;" : "=l"(d) : "l"(a), "l"(b), "l"(c)); return d;
}
__device__ __forceinline__ float2 unpack2(u64 v) {
    float2 f; asm("mov.b64 {%0,%1},%2;" : "=f"(f.x), "=f"(f.y) : "l"(v)); return f;
}
// pack two fp32 -> bf16x2 (first arg = hi half)
__device__ __forceinline__ uint32_t cvt_bf16x2(float hi, float lo) {
    uint32_t r; asm("cvt.rn.bf16x2.f32 %0, %1, %2;" : "=r"(r) : "f"(hi), "f"(lo)); return r;
}
// D(16x8,f32) += A(16x16,bf16) @ B(16x8,bf16)
__device__ __forceinline__ void mma16816(float& d0, float& d1, float& d2, float& d3,
        uint32_t a0, uint32_t a1, uint32_t a2, uint32_t a3,
        uint32_t b0, uint32_t b1) {
    asm("mma.sync.aligned.m16n8k16.row.col.f32.bf16.bf16.f32 "
        "{%0,%1,%2,%3}, {%4,%5,%6,%7}, {%8,%9}, {%0,%1,%2,%3};"
        : "+f"(d0), "+f"(d1), "+f"(d2), "+f"(d3)
        : "r"(a0), "r"(a1), "r"(a2), "r"(a3), "r"(b0), "r"(b1));
}

// Scratch (static device global; no dynamic allocation)
__device__ float g_Bt[(size_t)NV * KTAGS];   // emission table, word-major [w][k]

// ---------------------------------------------------------------------------
// Kernel 1: emission table g_Bt[w][k] = exp(dot(ThetaB[k,:], E[w,:]))
// ---------------------------------------------------------------------------
__global__ __launch_bounds__(256) void emit_table_kernel(
        const float* __restrict__ ThetaB, const float* __restrict__ E) {
    __shared__ __align__(16) float sE[64 * 65];
    __shared__ __align__(16) float sTh[64 * ASTR];

    int tid = threadIdx.x;
    int wq  = tid & 15;
    int kq  = tid >> 4;
    int w0  = blockIdx.x * 64;

    u64 acc[4][2];
#pragma unroll
    for (int a = 0; a < 4; a++) { acc[a][0] = 0ull; acc[a][1] = 0ull; }

    for (int dc = 0; dc < 2; dc++) {
        for (int idx = tid; idx < 64 * 64; idx += 256) {
            int k = idx >> 6, dl = idx & 63;
            sTh[dl * ASTR + k] = ThetaB[k * DDIM + dc * 64 + dl];
        }
        for (int idx = tid; idx < 64 * 64; idx += 256) {
            int w = idx >> 6, dl = idx & 63;
            int wg = w0 + w;
            sE[w * 65 + dl] = (wg < NV) ? E[(size_t)wg * DDIM + dc * 64 + dl] : 0.0f;
        }
        __syncthreads();

#pragma unroll 8
        for (int dl = 0; dl < 64; dl++) {
            ulonglong2 th = *(const ulonglong2*)&sTh[dl * ASTR + kq * 4];
#pragma unroll
            for (int ww = 0; ww < 4; ww++) {
                float e = sE[(wq * 4 + ww) * 65 + dl];
                u64 ep = pack2(e, e);
                acc[ww][0] = fma2(ep, th.x, acc[ww][0]);
                acc[ww][1] = fma2(ep, th.y, acc[ww][1]);
            }
        }
        __syncthreads();
    }

#pragma unroll
    for (int ww = 0; ww < 4; ww++) {
        int w = w0 + wq * 4 + ww;
        if (w < NV) {
            float2 p0 = unpack2(acc[ww][0]);
            float2 p1 = unpack2(acc[ww][1]);
            float4 r;
            r.x = expf(p0.x); r.y = expf(p0.y);
            r.z = expf(p1.x); r.w = expf(p1.y);
            if (kq == 15) { r.z = TINYV; r.w = TINYV; }
            *(float4*)&g_Bt[(size_t)w * KTAGS + kq * 4] = r;
        }
    }
}

// ---------------------------------------------------------------------------
// Kernel 2: forward scan via mma.sync m16n8k16 bf16, N-SPLIT across 4 warps.
// CTA = 128 threads = 4 warps, 16 sentences. Warp w owns output tags
// 16w..16w+15 (nb blocks 2w, 2w+1): 8 MMAs/step on its own SMSP tensor unit.
// Exchange: warp w's post-emission D fragment IS Af[kc=w] for everyone at the
// same lane -> 1 STS.128 + barrier + 4 LDS.128 per thread, no shuffles.
// Double-buffered exchange => one __syncthreads per step.
// lane: g = lane>>2 (sentence row, +8 for second), q = lane&3.
// ---------------------------------------------------------------------------
__global__ __launch_bounds__(128, 1) void crf_scan_kernel(
        const float* __restrict__ WA,
        const int* __restrict__ words, float* __restrict__ out) {
    __shared__ __align__(16) float sWA[KTAGS * KTAGS];   // 16 KB
    __shared__ int sWT[TLEN][16];                         // 16 KB
    __shared__ __align__(16) uint4 sX[2][4][32];          // 4 KB exchange
    __shared__ float sZ[4][16];

    int tid  = threadIdx.x;
    int w    = tid >> 5;      // warp 0..3 = output-tag block
    int lane = tid & 31;
    int g    = lane >> 2;     // 0..7
    int q    = lane & 3;      // 0..3
    int s0   = blockIdx.x * 16;

    for (int idx = tid; idx < KTAGS * KTAGS / 4; idx += 128)
        ((float4*)sWA)[idx] = ((const float4*)WA)[idx];
    for (int idx = tid; idx < 16 * TLEN; idx += 128) {
        int s = idx >> 8, tt = idx & (TLEN - 1);
        sWT[tt][s] = words[(size_t)(s0 + s) * TLEN + tt];
    }
    __syncthreads();

    // B fragments for own nb pair (j=0,1 -> nb = 2w+j, col n = 16w+8j+g)
    uint32_t Bf[4][2][2];
#pragma unroll
    for (int j = 0; j < 2; j++) {
        int n = 16 * w + 8 * j + g;
        bool bos = (n == BOS_TAG);
#pragma unroll
        for (int kc = 0; kc < 4; kc++) {
            int k0 = 16 * kc + 2 * q;
            float v0 = bos ? 0.0f : expf(sWA[(k0)     * KTAGS + n]) * SCL;
            float v1 = bos ? 0.0f : expf(sWA[(k0 + 1) * KTAGS + n]) * SCL;
            float v8 = bos ? 0.0f : expf(sWA[(k0 + 8) * KTAGS + n]) * SCL;
            float v9 = bos ? 0.0f : expf(sWA[(k0 + 9) * KTAGS + n]) * SCL;
            Bf[kc][j][0] = cvt_bf16x2(v1, v0);
            Bf[kc][j][1] = cvt_bf16x2(v9, v8);
        }
    }

    // EOS column entries for this thread's 4 tags
    float eos0[2], eos1[2];
#pragma unroll
    for (int j = 0; j < 2; j++) {
        int n0 = 16 * w + 8 * j + 2 * q;
        eos0[j] = expf(sWA[(n0)     * KTAGS + EOS_TAG]) * SCL;
        eos1[j] = expf(sWA[(n0 + 1) * KTAGS + EOS_TAG]) * SCL;
    }

    // alpha_1[s][n] = A'[BOS][n] * emis(pos 1)[n], fp32, own 16-tag slice
    float d[2][4];
    {
        int w1g  = sWT[1][g];
        int w1g8 = sWT[1][8 + g];
#pragma unroll
        for (int j = 0; j < 2; j++) {
            int n0 = 16 * w + 8 * j + 2 * q;
            float rb0 = (n0     == BOS_TAG) ? 0.0f : expf(sWA[BOS_TAG * KTAGS + n0])     * SCL;
            float rb1 = (n0 + 1 == BOS_TAG) ? 0.0f : expf(sWA[BOS_TAG * KTAGS + n0 + 1]) * SCL;
            float2 eA = *(const float2*)(g_Bt + (size_t)w1g  * KTAGS + n0);
            float2 eB = *(const float2*)(g_Bt + (size_t)w1g8 * KTAGS + n0);
            d[j][0] = rb0 * eA.x; d[j][1] = rb1 * eA.y;
            d[j][2] = rb0 * eB.x; d[j][3] = rb1 * eB.y;
        }
    }

    // prefetch emissions for step t=2 (own 4 tags, both sentence rows)
    float2 eg[2], eg8[2];
    {
        int w2g  = sWT[2][g];
        int w2g8 = sWT[2][8 + g];
#pragma unroll
        for (int j = 0; j < 2; j++) {
            int n0 = 16 * w + 8 * j + 2 * q;
            eg[j]  = *(const float2*)(g_Bt + (size_t)w2g  * KTAGS + n0);
            eg8[j] = *(const float2*)(g_Bt + (size_t)w2g8 * KTAGS + n0);
        }
    }

    int p = 0;
    for (int t = 2; t <= TLEN - 2; ++t) {
        // publish own Af[w] slice (alpha_{t-1}, bf16)
        uint4 my;
        my.x = cvt_bf16x2(d[0][1], d[0][0]);
        my.y = cvt_bf16x2(d[0][3], d[0][2]);
        my.z = cvt_bf16x2(d[1][1], d[1][0]);
        my.w = cvt_bf16x2(d[1][3], d[1][2]);
        sX[p][w][lane] = my;
        __syncthreads();

        // prefetch emissions for t+1 (t=254 reads pos 255: valid, unused)
        float2 ng[2], ng8[2];
        {
            int wn  = sWT[t + 1][g];
            int wn8 = sWT[t + 1][8 + g];
#pragma unroll
            for (int j = 0; j < 2; j++) {
                int n0 = 16 * w + 8 * j + 2 * q;
                ng[j]  = *(const float2*)(g_Bt + (size_t)wn  * KTAGS + n0);
                ng8[j] = *(const float2*)(g_Bt + (size_t)wn8 * KTAGS + n0);
            }
        }

        // gather full alpha fragment set
        uint32_t Af[4][4];
#pragma unroll
        for (int kc = 0; kc < 4; kc++) {
            uint4 v = sX[p][kc][lane];
            Af[kc][0] = v.x; Af[kc][1] = v.y; Af[kc][2] = v.z; Af[kc][3] = v.w;
        }

        // D = alpha_{t-1} @ A'[:, own 16 cols]
#pragma unroll
        for (int j = 0; j < 2; j++) {
            d[j][0] = 0.0f; d[j][1] = 0.0f; d[j][2] = 0.0f; d[j][3] = 0.0f;
#pragma unroll
            for (int kc = 0; kc < 4; kc++)
                mma16816(d[j][0], d[j][1], d[j][2], d[j][3],
                         Af[kc][0], Af[kc][1], Af[kc][2], Af[kc][3],
                         Bf[kc][j][0], Bf[kc][j][1]);
        }

        // x emissions (fp32)
#pragma unroll
        for (int j = 0; j < 2; j++) {
            d[j][0] *= eg[j].x;  d[j][1] *= eg[j].y;
            d[j][2] *= eg8[j].x; d[j][3] *= eg8[j].y;
            eg[j] = ng[j]; eg8[j] = ng8[j];
        }
        p ^= 1;
    }

    // final transition into EOS: partial over own 16 tags, then cross-warp sum
    {
        float zg = 0.0f, zg8 = 0.0f;
#pragma unroll
        for (int j = 0; j < 2; j++) {
            zg  += d[j][0] * eos0[j] + d[j][1] * eos1[j];
            zg8 += d[j][2] * eos0[j] + d[j][3] * eos1[j];
        }
        zg  += __shfl_xor_sync(0xffffffffu, zg, 1);
        zg  += __shfl_xor_sync(0xffffffffu, zg, 2);
        zg8 += __shfl_xor_sync(0xffffffffu, zg8, 1);
        zg8 += __shfl_xor_sync(0xffffffffu, zg8, 2);
        if (q == 0) {
            sZ[w][g]     = zg;
            sZ[w][8 + g] = zg8;
        }
    }
    __syncthreads();
    if (tid < 16) {
        float z = sZ[0][tid] + sZ[1][tid] + sZ[2][tid] + sZ[3][tid];
        // + 255 * log(64) = 1530 * ln2 (fixed-scaling compensation)
        out[s0 + tid] = logf(z) + 1060.5151862567153f;
    }
}

// ---------------------------------------------------------------------------
extern "C" void kernel_launch(void* const* d_in, const int* in_sizes, int n_in,
                              void* d_out, int out_size) {
    const int*   words  = nullptr;
    const float* ThetaB = nullptr;
    const float* WA     = nullptr;
    const float* E      = nullptr;
    for (int i = 0; i < n_in; i++) {
        switch (in_sizes[i]) {
            case BATCHN * TLEN:   words  = (const int*)d_in[i];   break;
            case KTAGS * DDIM:    ThetaB = (const float*)d_in[i]; break;
            case KTAGS * KTAGS:   WA     = (const float*)d_in[i]; break;
            case NV * DDIM:       E      = (const float*)d_in[i]; break;
        }
    }
    float* out = (float*)d_out;

    emit_table_kernel<<<(NV + 63) / 64, 256>>>(ThetaB, E);
    crf_scan_kernel<<<BATCHN / 16, 128>>>(WA, words, out);
}